// round 12
// baseline (speedup 1.0000x reference)
#include <cuda_runtime.h>
#include <cuda_bf16.h>
#include <cstdint>

#define Bn 512
#define Sn 128
#define Hn 1024
#define Ln 20
#define On 6

// ---------------- device scratch (no allocations allowed) -------------------
__device__ float g_x [Bn*Hn];
__device__ float g_xn[Bn*Hn];
__device__ float g_db2[Ln*Hn];
// Triple-K packed bf16 operands: C = AhBh + AhBl + AlBh via K'' = 3K
__device__ __nv_bfloat16 g1A[Hn*3*Bn];   // we^T: [j][ weTh(512) | weTh | weTl ]
__device__ __nv_bfloat16 g1B[Hn*3*Bn];   // x^T : [k][ xTh(512)  | xTl  | xTh  ]
__device__ __nv_bfloat16 g2A[Bn*3*Hn];   // x   : [b][ xh(1024)  | xh   | xl   ]
__device__ __nv_bfloat16 g2B[Hn*3*Hn];   // W   : [j][ Wh(1024)  | Wl   | Wh   ]

__constant__ float c_secw[4] = {0.92f, 1.08f, 0.98f, 1.05f};

// ---------------- helpers ----------------------------------------------------
__device__ __forceinline__ uint32_t smem_u32(const void* p) {
    uint32_t a;
    asm("{ .reg .u64 t; cvta.to.shared.u64 t, %1; cvt.u32.u64 %0, t; }" : "=r"(a) : "l"(p));
    return a;
}
__device__ __forceinline__ void cp16(uint32_t dst, const void* src) {
    asm volatile("cp.async.cg.shared.global [%0], [%1], 16;" :: "r"(dst), "l"(src));
}
#define CP_COMMIT() asm volatile("cp.async.commit_group;" ::: "memory")

__device__ __forceinline__ void ldm_x4(uint32_t& r0, uint32_t& r1, uint32_t& r2,
                                       uint32_t& r3, uint32_t addr) {
    asm volatile("ldmatrix.sync.aligned.m8n8.x4.shared.b16 {%0,%1,%2,%3}, [%4];"
                 : "=r"(r0), "=r"(r1), "=r"(r2), "=r"(r3) : "r"(addr));
}
__device__ __forceinline__ void mma16816(float* c, const uint32_t* a,
                                         const uint32_t* b) {
    asm volatile("mma.sync.aligned.m16n8k16.row.col.f32.bf16.bf16.f32 "
                 "{%0,%1,%2,%3}, {%4,%5,%6,%7}, {%8,%9}, {%0,%1,%2,%3};"
                 : "+f"(c[0]), "+f"(c[1]), "+f"(c[2]), "+f"(c[3])
                 : "r"(a[0]), "r"(a[1]), "r"(a[2]), "r"(a[3]), "r"(b[0]), "r"(b[1]));
}
__device__ __forceinline__ void split2(float v0, float v1, uint32_t& hw, uint32_t& lw) {
    __nv_bfloat16 h0 = __float2bfloat16(v0);
    __nv_bfloat16 h1 = __float2bfloat16(v1);
    __nv_bfloat16 l0 = __float2bfloat16(v0 - __bfloat162float(h0));
    __nv_bfloat16 l1 = __float2bfloat16(v1 - __bfloat162float(h1));
    hw = ((uint32_t)__bfloat16_as_ushort(h1) << 16) | __bfloat16_as_ushort(h0);
    lw = ((uint32_t)__bfloat16_as_ushort(l1) << 16) | __bfloat16_as_ushort(l0);
}

// ---------------------------------------------------------------------------
// GEMM core: 64(M) x NT(N) CTA tile, BK=32, 3-stage cp.async, one sync/iter.
// 8 warps as 2(m) x 4(n); warp tile 32 x NT/4.
// smem rows padded to 80B (conflict-free ldmatrix).
// ---------------------------------------------------------------------------
template <int NT>
__device__ __forceinline__ void gemm_core(const char* gA, const char* gB,
                                          int k2b, int KT, char* sm,
                                          float (*C)[4]) {
    constexpr int BUF = (64 + NT) * 80;     // bytes per stage
    constexpr int NB  = NT / 32;            // n8-tiles per warp
    const int tid = threadIdx.x;
    const int lane = tid & 31, wid = tid >> 5;
    const int wm = wid >> 2, wn = wid & 3;
    const uint32_t s0 = smem_u32(sm);
    const int row_off = ((lane >> 3) & 1) * 8 + (lane & 7);
    const int chsel   = lane >> 4;

#define LOADTILE(kt, buf) do {                                                  \
    const uint32_t sa = s0 + (buf)*BUF;                                         \
    const uint32_t sb = sa + 5120;                                              \
    { int r = tid >> 2, ch = tid & 3;                                           \
      cp16(sa + r*80 + ch*16, gA + (size_t)r*k2b + (kt)*64 + ch*16); }          \
    _Pragma("unroll")                                                           \
    for (int i = 0; i < NT/64; ++i) {                                           \
        int idx = tid + i*256; int r = idx >> 2, ch = idx & 3;                  \
        cp16(sb + r*80 + ch*16, gB + (size_t)r*k2b + (kt)*64 + ch*16);          \
    }                                                                           \
    CP_COMMIT(); } while (0)

    LOADTILE(0, 0);
    LOADTILE(1, 1);
    int buf = 0;
    for (int kt = 0; kt < KT; ++kt) {
        if (kt + 1 < KT) asm volatile("cp.async.wait_group 1;" ::: "memory");
        else             asm volatile("cp.async.wait_group 0;" ::: "memory");
        __syncthreads();
        if (kt + 2 < KT) {
            int nb = buf + 2; if (nb >= 3) nb -= 3;
            LOADTILE(kt + 2, nb);
        }
        const uint32_t sa = s0 + buf*BUF;
        const uint32_t sb = sa + 5120;
#pragma unroll
        for (int ks = 0; ks < 2; ++ks) {
            const int kb = ks * 32;
            uint32_t a[2][4], bfr[NB][2];
#pragma unroll
            for (int mt = 0; mt < 2; ++mt)
                ldm_x4(a[mt][0], a[mt][1], a[mt][2], a[mt][3],
                       sa + (uint32_t)(wm*32 + mt*16 + row_off)*80 + kb + chsel*16);
#pragma unroll
            for (int bt = 0; bt < NT/64; ++bt) {
                uint32_t r0, r1, r2, r3;
                ldm_x4(r0, r1, r2, r3,
                       sb + (uint32_t)(wn*(NT/4) + bt*16 + row_off)*80 + kb + chsel*16);
                bfr[bt*2+0][0] = r0; bfr[bt*2+1][0] = r1;
                bfr[bt*2+0][1] = r2; bfr[bt*2+1][1] = r3;
            }
#pragma unroll
            for (int mt = 0; mt < 2; ++mt)
#pragma unroll
                for (int nt = 0; nt < NB; ++nt)
                    mma16816(C[mt*NB+nt], a[mt], bfr[nt]);
        }
        buf = (buf + 1 == 3) ? 0 : buf + 1;
    }
#undef LOADTILE
}

// ---------------------------------------------------------------------------
// embed mean-pool -> g_x
// ---------------------------------------------------------------------------
__global__ __launch_bounds__(256) void k_embed(const int* __restrict__ X,
                                               const float* __restrict__ embed) {
    __shared__ int sidx[Sn];
    const int b = blockIdx.x, t = threadIdx.x;
    if (t < Sn) sidx[t] = X[b*Sn + t];
    __syncthreads();
    float4 acc = make_float4(0.f, 0.f, 0.f, 0.f);
#pragma unroll 4
    for (int s = 0; s < Sn; ++s) {
        const float4* row = reinterpret_cast<const float4*>(embed) + (size_t)sidx[s]*(Hn/4);
        float4 v = __ldg(row + t);
        acc.x += v.x; acc.y += v.y; acc.z += v.z; acc.w += v.w;
    }
    const float inv = 1.0f / Sn;
    reinterpret_cast<float4*>(g_x)[b*(Hn/4) + t] =
        make_float4(acc.x*inv, acc.y*inv, acc.z*inv, acc.w*inv);
}

__global__ void k_zero() { g_db2[blockIdx.x*1024 + threadIdx.x] = 0.f; }

// ---------------------------------------------------------------------------
// prep: per layer — we, hi/lo splits into triple-K packs, db reduce
// grid (Hn/32, Bn/32), block 256 (32x8)
// ---------------------------------------------------------------------------
__global__ __launch_bounds__(256) void k_prep(const int* __restrict__ eids,
                                              const float* __restrict__ wi_,
                                              const float* __restrict__ wh_,
                                              int layer, int flip) {
    const float* __restrict__ x = flip ? g_xn : g_x;
    __shared__ float sx[32][33], swe[32][33], sdb[32][9];
    const int tx = threadIdx.x & 31, ty = threadIdx.x >> 5;
    const int j0 = blockIdx.x*32, b0 = blockIdx.y*32;
    const float wiv = __ldg(wi_ + layer), whv = __ldg(wh_ + layer);
    float dbp = 0.f;
#pragma unroll
    for (int i = 0; i < 4; ++i) {
        const int bl = ty + i*8, b = b0 + bl;
        const float xv = x[b*Hn + j0 + tx];
        const float cc = 3.14159265358979f * (float)__ldg(eids + b) * whv;
        const float we = wiv * sinf(cc * xv);
        sx[bl][tx] = xv; swe[bl][tx] = we;
        dbp += we;
        __nv_bfloat16 h = __float2bfloat16(xv);
        __nv_bfloat16 l = __float2bfloat16(xv - __bfloat162float(h));
        __nv_bfloat16* row = g2A + (size_t)b*(3*Hn);
        row[j0 + tx] = h; row[Hn + j0 + tx] = h; row[2*Hn + j0 + tx] = l;
    }
    sdb[tx][ty] = dbp;
    __syncthreads();
    if (ty == 0) {
        float s = 0.f;
#pragma unroll
        for (int k = 0; k < 8; ++k) s += sdb[tx][k];
        atomicAdd(&g_db2[layer*Hn + j0 + tx], s * (1.0f/Bn));
    }
#pragma unroll
    for (int i = 0; i < 4; ++i) {
        const int jl = ty + i*8, j = j0 + jl;
        float xv = sx[tx][jl];
        __nv_bfloat16 xh = __float2bfloat16(xv);
        __nv_bfloat16 xl = __float2bfloat16(xv - __bfloat162float(xh));
        __nv_bfloat16* rb = g1B + (size_t)j*(3*Bn);
        rb[b0 + tx] = xh; rb[Bn + b0 + tx] = xl; rb[2*Bn + b0 + tx] = xh;
        float wv = swe[tx][jl];
        __nv_bfloat16 wh2 = __float2bfloat16(wv);
        __nv_bfloat16 wl2 = __float2bfloat16(wv - __bfloat162float(wh2));
        __nv_bfloat16* ra = g1A + (size_t)j*(3*Bn);
        ra[b0 + tx] = wh2; ra[Bn + b0 + tx] = wh2; ra[2*Bn + b0 + tx] = wl2;
    }
}

// ---------------------------------------------------------------------------
// GEMM1: W[j,k] = waveW[i] + (we^T x)/B; 64(M=j) x 128(N=k) tiles, K''=1536
// grid (8,16) block 256. Epilogue packs W into g2B triple-K.
// ---------------------------------------------------------------------------
__global__ __launch_bounds__(256) void k_g1(const float* __restrict__ waveW, int layer) {
    __shared__ __align__(16) char sm[3*(64+128)*80];
    const int k0 = blockIdx.x*128, j0 = blockIdx.y*64;
    float C[8][4] = {};
    gemm_core<128>((const char*)(g1A + (size_t)j0*(3*Bn)),
                   (const char*)(g1B + (size_t)k0*(3*Bn)),
                   3*Bn*2, (3*Bn)/32, sm, C);

    const int lane = threadIdx.x & 31, wid = threadIdx.x >> 5;
    const int wm = wid >> 2, wn = wid & 3;
    const float invB = 1.0f/Bn;
    const float* wbase = waveW + (size_t)layer*Hn*Hn;
#pragma unroll
    for (int mt = 0; mt < 2; ++mt)
#pragma unroll
    for (int nt = 0; nt < 4; ++nt)
#pragma unroll
    for (int half = 0; half < 2; ++half) {
        const int j = j0 + wm*32 + mt*16 + (lane >> 2) + half*8;
        const int k = k0 + wn*32 + nt*8 + (lane & 3)*2;
        const float2 w = *reinterpret_cast<const float2*>(wbase + (size_t)j*Hn + k);
        const float v0 = w.x + C[mt*4+nt][half*2+0]*invB;
        const float v1 = w.y + C[mt*4+nt][half*2+1]*invB;
        uint32_t hw, lw; split2(v0, v1, hw, lw);
        uint32_t* row = reinterpret_cast<uint32_t*>(g2B + (size_t)j*(3*Hn));
        row[(k) >> 1] = hw; row[(Hn + k) >> 1] = lw; row[(2*Hn + k) >> 1] = hw;
    }
}

// ---------------------------------------------------------------------------
// GEMM2: xn = act(x @ W^T + bias); 64(M=b) x 64(N=j) tiles, K''=3072
// grid (16,8) block 256 -> 128 CTAs. Epilogue: bias + act + PReLU, fp32 out.
// ---------------------------------------------------------------------------
__global__ __launch_bounds__(256) void k_g2(const float* __restrict__ waveb,
                                            const float* __restrict__ a_table,
                                            const int* __restrict__ eids,
                                            const int* __restrict__ elab,
                                            int layer, int flip) {
    float* __restrict__ xn = flip ? g_x : g_xn;
    __shared__ __align__(16) char sm[3*(64+64)*80];
    __shared__ float sbias[64];
    const int j0 = blockIdx.x*64, b0 = blockIdx.y*64;
    if (threadIdx.x < 64)
        sbias[threadIdx.x] = g_db2[layer*Hn + j0 + threadIdx.x]
                           + __ldg(waveb + layer*Hn + j0 + threadIdx.x);
    float C[4][4] = {};
    gemm_core<64>((const char*)(g2A + (size_t)b0*(3*Hn)),
                  (const char*)(g2B + (size_t)j0*(3*Hn)),
                  3*Hn*2, (3*Hn)/32, sm, C);

    const int lane = threadIdx.x & 31, wid = threadIdx.x >> 5;
    const int wm = wid >> 2, wn = wid & 3;
    const int mode = layer % 3;
#pragma unroll
    for (int mt = 0; mt < 2; ++mt)
#pragma unroll
    for (int half = 0; half < 2; ++half) {
        const int b = b0 + wm*32 + mt*16 + (lane >> 2) + half*8;
        const float slope = __ldg(a_table + __ldg(eids + b)*Ln + layer)
                          * c_secw[__ldg(elab + b)];
#pragma unroll
        for (int nt = 0; nt < 2; ++nt) {
            const int j = j0 + wn*16 + nt*8 + (lane & 3)*2;
            float v[2];
#pragma unroll
            for (int e = 0; e < 2; ++e) {
                float r = C[mt*2+nt][half*2+e] + sbias[j - j0 + e];
                float z;
                if (mode == 0)      z = tanhf(r);
                else if (mode == 1) z = sinf(r);
                else                z = fmaxf(r, 0.f);
                v[e] = (z > 0.f) ? z : slope * z;
            }
            *reinterpret_cast<float2*>(xn + (size_t)b*Hn + j) = make_float2(v[0], v[1]);
        }
    }
}

// ---------------------------------------------------------------------------
// head: out = x @ fc_W^T + fc_b
// ---------------------------------------------------------------------------
__global__ __launch_bounds__(256) void k_out(const float* __restrict__ fcW,
                                             const float* __restrict__ fcb,
                                             float* __restrict__ out, int flip) {
    const float* __restrict__ x = flip ? g_xn : g_x;
    const int b = blockIdx.x, o = blockIdx.y, t = threadIdx.x;
    float acc = 0.f;
    for (int k = t; k < Hn; k += 256)
        acc += x[b*Hn + k] * fcW[o*Hn + k];
#pragma unroll
    for (int off = 16; off; off >>= 1)
        acc += __shfl_xor_sync(0xffffffff, acc, off);
    __shared__ float sred[8];
    if ((t & 31) == 0) sred[t >> 5] = acc;
    __syncthreads();
    if (t == 0) {
        float s = 0.f;
#pragma unroll
        for (int w = 0; w < 8; ++w) s += sred[w];
        out[b*On + o] = s + fcb[o];
    }
}

// ---------------------------------------------------------------------------
extern "C" void kernel_launch(void* const* d_in, const int* in_sizes, int n_in,
                              void* d_out, int out_size) {
    (void)in_sizes; (void)n_in; (void)out_size;
    const int*   X     = (const int*)  d_in[0];
    const int*   eids  = (const int*)  d_in[1];
    const int*   elab  = (const int*)  d_in[2];
    const float* embed = (const float*)d_in[3];
    const float* waveW = (const float*)d_in[4];
    const float* waveb = (const float*)d_in[5];
    const float* wi    = (const float*)d_in[6];
    const float* wh    = (const float*)d_in[7];
    const float* atab  = (const float*)d_in[8];
    const float* fcW   = (const float*)d_in[9];
    const float* fcb   = (const float*)d_in[10];
    float* out = (float*)d_out;

    k_embed<<<Bn, 256>>>(X, embed);
    k_zero<<<Ln, 1024>>>();
    for (int i = 0; i < Ln; ++i) {
        const int flip = i & 1;
        k_prep<<<dim3(Hn/32, Bn/32), 256>>>(eids, wi, wh, i, flip);
        k_g1<<<dim3(8, 16), 256>>>(waveW, i);
        k_g2<<<dim3(16, 8), 256>>>(waveb, atab, eids, elab, i, flip);
    }
    k_out<<<dim3(Bn, On), 256>>>(fcW, fcb, out, Ln & 1);
}

// round 14
// speedup vs baseline: 1.3568x; 1.3568x over previous
#include <cuda_runtime.h>
#include <cuda_bf16.h>
#include <cstdint>

#define Bn 512
#define Sn 128
#define Hn 1024
#define Ln 20
#define On 6

// ---------------- device scratch (no allocations allowed) -------------------
__device__ float g_x [Bn*Hn];
__device__ float g_xn[Bn*Hn];
__device__ float g_db2[Ln*Hn];
// Triple-K packed bf16 operands: C = AhBh + AhBl + AlBh via K'' = 3K
__device__ __nv_bfloat16 g1A[Hn*3*Bn];   // we^T: [j][ weTh(512) | weTh | weTl ]
__device__ __nv_bfloat16 g1B[Hn*3*Bn];   // x^T : [k][ xTh(512)  | xTl  | xTh  ]
__device__ __nv_bfloat16 g2A[Bn*3*Hn];   // x   : [b][ xh(1024)  | xh   | xl   ]
__device__ __nv_bfloat16 g2B[Hn*3*Hn];   // W   : [j][ Wh(1024)  | Wl   | Wh   ]

__constant__ float c_secw[4] = {0.92f, 1.08f, 0.98f, 1.05f};

// ---------------- helpers ----------------------------------------------------
__device__ __forceinline__ uint32_t smem_u32(const void* p) {
    uint32_t a;
    asm("{ .reg .u64 t; cvta.to.shared.u64 t, %1; cvt.u32.u64 %0, t; }" : "=r"(a) : "l"(p));
    return a;
}
__device__ __forceinline__ void cp16(uint32_t dst, const void* src) {
    asm volatile("cp.async.cg.shared.global [%0], [%1], 16;" :: "r"(dst), "l"(src));
}
#define CP_COMMIT() asm volatile("cp.async.commit_group;" ::: "memory")

__device__ __forceinline__ void ldm_x4(uint32_t& r0, uint32_t& r1, uint32_t& r2,
                                       uint32_t& r3, uint32_t addr) {
    asm volatile("ldmatrix.sync.aligned.m8n8.x4.shared.b16 {%0,%1,%2,%3}, [%4];"
                 : "=r"(r0), "=r"(r1), "=r"(r2), "=r"(r3) : "r"(addr));
}
__device__ __forceinline__ void mma16816(float* c, const uint32_t* a,
                                         const uint32_t* b) {
    asm volatile("mma.sync.aligned.m16n8k16.row.col.f32.bf16.bf16.f32 "
                 "{%0,%1,%2,%3}, {%4,%5,%6,%7}, {%8,%9}, {%0,%1,%2,%3};"
                 : "+f"(c[0]), "+f"(c[1]), "+f"(c[2]), "+f"(c[3])
                 : "r"(a[0]), "r"(a[1]), "r"(a[2]), "r"(a[3]), "r"(b[0]), "r"(b[1]));
}
__device__ __forceinline__ void split2(float v0, float v1, uint32_t& hw, uint32_t& lw) {
    __nv_bfloat16 h0 = __float2bfloat16(v0);
    __nv_bfloat16 h1 = __float2bfloat16(v1);
    __nv_bfloat16 l0 = __float2bfloat16(v0 - __bfloat162float(h0));
    __nv_bfloat16 l1 = __float2bfloat16(v1 - __bfloat162float(h1));
    hw = ((uint32_t)__bfloat16_as_ushort(h1) << 16) | __bfloat16_as_ushort(h0);
    lw = ((uint32_t)__bfloat16_as_ushort(l1) << 16) | __bfloat16_as_ushort(l0);
}

// ---------------------------------------------------------------------------
// GEMM core: MT(M) x NT(N) CTA tile, BK=32, 2-stage cp.async, 128 threads.
// 4 warps as 2(m) x 2(n); warp tile (MT/2) x (NT/2).
// smem rows padded to 80B (conflict-free ldmatrix / cp.async).
// C layout: C[mt*(NT/16) + nt][4]
// ---------------------------------------------------------------------------
template <int MT, int NT>
__device__ __forceinline__ void gemm_core(const char* gA, const char* gB,
                                          int k2b, int KT, char* sm,
                                          float (*C)[4]) {
    constexpr int BUF = (MT + NT) * 80;
    constexpr int MB  = MT / 32;           // m16 tiles per warp
    constexpr int NBT = NT / 32;           // B ldm_x4 per warp (16 rows each)
    constexpr int NB  = NT / 16;           // n8 tiles per warp
    const int tid = threadIdx.x;
    const int lane = tid & 31, wid = tid >> 5;
    const int wm = wid >> 1, wn = wid & 1;
    const uint32_t s0 = smem_u32(sm);
    const int row_off = ((lane >> 3) & 1) * 8 + (lane & 7);
    const int chsel   = lane >> 4;

#define LOADTILE(kt, buf) do {                                                  \
    const uint32_t sa = s0 + (buf)*BUF;                                         \
    const uint32_t sb = sa + MT*80;                                             \
    _Pragma("unroll")                                                           \
    for (int i = 0; i < (MT + NT)/32; ++i) {                                    \
        int idx = tid + i*128; int r = idx >> 2, ch = idx & 3;                  \
        if (r < MT) cp16(sa + r*80 + ch*16, gA + (size_t)r*k2b + (kt)*64 + ch*16); \
        else { int rr = r - MT;                                                 \
               cp16(sb + rr*80 + ch*16, gB + (size_t)rr*k2b + (kt)*64 + ch*16); } \
    }                                                                           \
    CP_COMMIT(); } while (0)

    LOADTILE(0, 0);
    for (int kt = 0; kt < KT; ++kt) {
        if (kt + 1 < KT) {
            LOADTILE(kt + 1, (kt + 1) & 1);
            asm volatile("cp.async.wait_group 1;" ::: "memory");
        } else {
            asm volatile("cp.async.wait_group 0;" ::: "memory");
        }
        __syncthreads();
        const uint32_t sa = s0 + (kt & 1)*BUF;
        const uint32_t sb = sa + MT*80;
#pragma unroll
        for (int ks = 0; ks < 2; ++ks) {
            const int kb = ks * 32;
            uint32_t a[MB][4], bfr[NB][2];
#pragma unroll
            for (int mt = 0; mt < MB; ++mt)
                ldm_x4(a[mt][0], a[mt][1], a[mt][2], a[mt][3],
                       sa + (uint32_t)(wm*(MT/2) + mt*16 + row_off)*80 + kb + chsel*16);
#pragma unroll
            for (int bt = 0; bt < NBT; ++bt) {
                uint32_t r0, r1, r2, r3;
                ldm_x4(r0, r1, r2, r3,
                       sb + (uint32_t)(wn*(NT/2) + bt*16 + row_off)*80 + kb + chsel*16);
                bfr[bt*2+0][0] = r0; bfr[bt*2+1][0] = r1;
                bfr[bt*2+0][1] = r2; bfr[bt*2+1][1] = r3;
            }
#pragma unroll
            for (int mt = 0; mt < MB; ++mt)
#pragma unroll
                for (int nt = 0; nt < NB; ++nt)
                    mma16816(C[mt*NB+nt], a[mt], bfr[nt]);
        }
        __syncthreads();
    }
#undef LOADTILE
}

// ---------------------------------------------------------------------------
// embed mean-pool -> g_x
// ---------------------------------------------------------------------------
__global__ __launch_bounds__(256) void k_embed(const int* __restrict__ X,
                                               const float* __restrict__ embed) {
    __shared__ int sidx[Sn];
    const int b = blockIdx.x, t = threadIdx.x;
    if (t < Sn) sidx[t] = X[b*Sn + t];
    __syncthreads();
    float4 acc = make_float4(0.f, 0.f, 0.f, 0.f);
#pragma unroll 4
    for (int s = 0; s < Sn; ++s) {
        const float4* row = reinterpret_cast<const float4*>(embed) + (size_t)sidx[s]*(Hn/4);
        float4 v = __ldg(row + t);
        acc.x += v.x; acc.y += v.y; acc.z += v.z; acc.w += v.w;
    }
    const float inv = 1.0f / Sn;
    reinterpret_cast<float4*>(g_x)[b*(Hn/4) + t] =
        make_float4(acc.x*inv, acc.y*inv, acc.z*inv, acc.w*inv);
}

__global__ void k_zero() { g_db2[blockIdx.x*1024 + threadIdx.x] = 0.f; }

// ---------------------------------------------------------------------------
// prep: per layer — we, hi/lo splits into triple-K packs, db reduce
// grid (Hn/32, Bn/32), block 256 (32x8)
// ---------------------------------------------------------------------------
__global__ __launch_bounds__(256) void k_prep(const int* __restrict__ eids,
                                              const float* __restrict__ wi_,
                                              const float* __restrict__ wh_,
                                              int layer, int flip) {
    const float* __restrict__ x = flip ? g_xn : g_x;
    __shared__ float sx[32][33], swe[32][33], sdb[32][9];
    const int tx = threadIdx.x & 31, ty = threadIdx.x >> 5;
    const int j0 = blockIdx.x*32, b0 = blockIdx.y*32;
    const float wiv = __ldg(wi_ + layer), whv = __ldg(wh_ + layer);
    float dbp = 0.f;
#pragma unroll
    for (int i = 0; i < 4; ++i) {
        const int bl = ty + i*8, b = b0 + bl;
        const float xv = x[b*Hn + j0 + tx];
        const float cc = 3.14159265358979f * (float)__ldg(eids + b) * whv;
        const float we = wiv * sinf(cc * xv);
        sx[bl][tx] = xv; swe[bl][tx] = we;
        dbp += we;
        __nv_bfloat16 h = __float2bfloat16(xv);
        __nv_bfloat16 l = __float2bfloat16(xv - __bfloat162float(h));
        __nv_bfloat16* row = g2A + (size_t)b*(3*Hn);
        row[j0 + tx] = h; row[Hn + j0 + tx] = h; row[2*Hn + j0 + tx] = l;
    }
    sdb[tx][ty] = dbp;
    __syncthreads();
    if (ty == 0) {
        float s = 0.f;
#pragma unroll
        for (int k = 0; k < 8; ++k) s += sdb[tx][k];
        atomicAdd(&g_db2[layer*Hn + j0 + tx], s * (1.0f/Bn));
    }
#pragma unroll
    for (int i = 0; i < 4; ++i) {
        const int jl = ty + i*8, j = j0 + jl;
        float xv = sx[tx][jl];
        __nv_bfloat16 xh = __float2bfloat16(xv);
        __nv_bfloat16 xl = __float2bfloat16(xv - __bfloat162float(xh));
        __nv_bfloat16* rb = g1B + (size_t)j*(3*Bn);
        rb[b0 + tx] = xh; rb[Bn + b0 + tx] = xl; rb[2*Bn + b0 + tx] = xh;
        float wv = swe[tx][jl];
        __nv_bfloat16 wh2 = __float2bfloat16(wv);
        __nv_bfloat16 wl2 = __float2bfloat16(wv - __bfloat162float(wh2));
        __nv_bfloat16* ra = g1A + (size_t)j*(3*Bn);
        ra[b0 + tx] = wh2; ra[Bn + b0 + tx] = wh2; ra[2*Bn + b0 + tx] = wl2;
    }
}

// ---------------------------------------------------------------------------
// GEMM1: W[j,k] = waveW[i] + (we^T x)/B; 64(M=j) x 64(N=k) tiles, K''=1536
// grid (16,16) block 128 -> 256 CTAs. Epilogue packs W into g2B triple-K.
// ---------------------------------------------------------------------------
__global__ __launch_bounds__(128) void k_g1(const float* __restrict__ waveW, int layer) {
    __shared__ __align__(16) char sm[2*(64+64)*80];
    const int k0 = blockIdx.x*64, j0 = blockIdx.y*64;
    float C[8][4] = {};
    gemm_core<64,64>((const char*)(g1A + (size_t)j0*(3*Bn)),
                     (const char*)(g1B + (size_t)k0*(3*Bn)),
                     3*Bn*2, (3*Bn)/32, sm, C);

    const int lane = threadIdx.x & 31, wid = threadIdx.x >> 5;
    const int wm = wid >> 1, wn = wid & 1;
    const float invB = 1.0f/Bn;
    const float* wbase = waveW + (size_t)layer*Hn*Hn;
#pragma unroll
    for (int mt = 0; mt < 2; ++mt)
#pragma unroll
    for (int nt = 0; nt < 4; ++nt)
#pragma unroll
    for (int half = 0; half < 2; ++half) {
        const int j = j0 + wm*32 + mt*16 + (lane >> 2) + half*8;
        const int k = k0 + wn*32 + nt*8 + (lane & 3)*2;
        const float2 w = *reinterpret_cast<const float2*>(wbase + (size_t)j*Hn + k);
        const float v0 = w.x + C[mt*4+nt][half*2+0]*invB;
        const float v1 = w.y + C[mt*4+nt][half*2+1]*invB;
        uint32_t hw, lw; split2(v0, v1, hw, lw);
        uint32_t* row = reinterpret_cast<uint32_t*>(g2B + (size_t)j*(3*Hn));
        row[(k) >> 1] = hw; row[(Hn + k) >> 1] = lw; row[(2*Hn + k) >> 1] = hw;
    }
}

// ---------------------------------------------------------------------------
// GEMM2: xn = act(x @ W^T + bias); 64(M=b) x 32(N=j) tiles, K''=3072
// grid (32,8) block 128 -> 256 CTAs. Epilogue: bias + act + PReLU, fp32 out.
// ---------------------------------------------------------------------------
__global__ __launch_bounds__(128) void k_g2(const float* __restrict__ waveb,
                                            const float* __restrict__ a_table,
                                            const int* __restrict__ eids,
                                            const int* __restrict__ elab,
                                            int layer, int flip) {
    float* __restrict__ xn = flip ? g_x : g_xn;
    __shared__ __align__(16) char sm[2*(64+32)*80];
    __shared__ float sbias[32];
    const int j0 = blockIdx.x*32, b0 = blockIdx.y*64;
    if (threadIdx.x < 32)
        sbias[threadIdx.x] = g_db2[layer*Hn + j0 + threadIdx.x]
                           + __ldg(waveb + layer*Hn + j0 + threadIdx.x);
    float C[4][4] = {};
    gemm_core<64,32>((const char*)(g2A + (size_t)b0*(3*Hn)),
                     (const char*)(g2B + (size_t)j0*(3*Hn)),
                     3*Hn*2, (3*Hn)/32, sm, C);

    const int lane = threadIdx.x & 31, wid = threadIdx.x >> 5;
    const int wm = wid >> 1, wn = wid & 1;
    const int mode = layer % 3;
#pragma unroll
    for (int mt = 0; mt < 2; ++mt)
#pragma unroll
    for (int half = 0; half < 2; ++half) {
        const int b = b0 + wm*32 + mt*16 + (lane >> 2) + half*8;
        const float slope = __ldg(a_table + __ldg(eids + b)*Ln + layer)
                          * c_secw[__ldg(elab + b)];
#pragma unroll
        for (int nt = 0; nt < 2; ++nt) {
            const int j = j0 + wn*16 + nt*8 + (lane & 3)*2;
            float v[2];
#pragma unroll
            for (int e = 0; e < 2; ++e) {
                float r = C[mt*2+nt][half*2+e] + sbias[j - j0 + e];
                float z;
                if (mode == 0)      z = tanhf(r);
                else if (mode == 1) z = sinf(r);
                else                z = fmaxf(r, 0.f);
                v[e] = (z > 0.f) ? z : slope * z;
            }
            *reinterpret_cast<float2*>(xn + (size_t)b*Hn + j) = make_float2(v[0], v[1]);
        }
    }
}

// ---------------------------------------------------------------------------
// head: out = x @ fc_W^T + fc_b
// ---------------------------------------------------------------------------
__global__ __launch_bounds__(256) void k_out(const float* __restrict__ fcW,
                                             const float* __restrict__ fcb,
                                             float* __restrict__ out, int flip) {
    const float* __restrict__ x = flip ? g_xn : g_x;
    const int b = blockIdx.x, o = blockIdx.y, t = threadIdx.x;
    float acc = 0.f;
    for (int k = t; k < Hn; k += 256)
        acc += x[b*Hn + k] * fcW[o*Hn + k];
#pragma unroll
    for (int off = 16; off; off >>= 1)
        acc += __shfl_xor_sync(0xffffffff, acc, off);
    __shared__ float sred[8];
    if ((t & 31) == 0) sred[t >> 5] = acc;
    __syncthreads();
    if (t == 0) {
        float s = 0.f;
#pragma unroll
        for (int w = 0; w < 8; ++w) s += sred[w];
        out[b*On + o] = s + fcb[o];
    }
}

// ---------------------------------------------------------------------------
extern "C" void kernel_launch(void* const* d_in, const int* in_sizes, int n_in,
                              void* d_out, int out_size) {
    (void)in_sizes; (void)n_in; (void)out_size;
    const int*   X     = (const int*)  d_in[0];
    const int*   eids  = (const int*)  d_in[1];
    const int*   elab  = (const int*)  d_in[2];
    const float* embed = (const float*)d_in[3];
    const float* waveW = (const float*)d_in[4];
    const float* waveb = (const float*)d_in[5];
    const float* wi    = (const float*)d_in[6];
    const float* wh    = (const float*)d_in[7];
    const float* atab  = (const float*)d_in[8];
    const float* fcW   = (const float*)d_in[9];
    const float* fcb   = (const float*)d_in[10];
    float* out = (float*)d_out;

    k_embed<<<Bn, 256>>>(X, embed);
    k_zero<<<Ln, 1024>>>();
    for (int i = 0; i < Ln; ++i) {
        const int flip = i & 1;
        k_prep<<<dim3(Hn/32, Bn/32), 256>>>(eids, wi, wh, i, flip);
        k_g1<<<dim3(16, 16), 128>>>(waveW, i);
        k_g2<<<dim3(32, 8), 128>>>(waveb, atab, eids, elab, i, flip);
    }
    k_out<<<dim3(Bn, On), 256>>>(fcW, fcb, out, Ln & 1);
}